// round 1
// baseline (speedup 1.0000x reference)
#include <cuda_runtime.h>

// Problem constants
#define BB   64
#define NN   883
#define EE   10
#define CINx 66     // DIN + DOUT
#define DO   64     // DOUT
#define OG   128    // gate output width (2*DOUT)
#define OU   64     // update output width

// L@x tiling
#define TN   16     // rows per block
#define TM   64     // m-tile
#define CP   68     // padded channel count (66 -> 68, /4 = 17 groups)
#define CGc  17     // channel groups of 4

// ---------------- scratch (device globals; no allocation allowed) ----------------
__device__ float g_Wg[NN * 2 * CINx * OG];   // per-node gate weights   (59.7 MB)
__device__ float g_bg[NN * OG];
__device__ float g_Wu[NN * 2 * CINx * OU];   // per-node update weights (29.8 MB)
__device__ float g_bu[NN * OU];
__device__ float g_xs[BB * NN * CINx];       // current DGCN input (concat)
__device__ float g_nv[BB * NN * EE];         // nodevec
__device__ float g_d[BB * NN];               // degree^-0.5
__device__ float g_dxs[BB * NN * CINx];      // d[m] * xs[m, c]
__device__ float g_y2[BB * NN * CINx];       // L @ xs
__device__ float g_zr[BB * NN * OG];         // sigmoid(gate out): z | r

__device__ __forceinline__ float sigm(float v) { return 1.f / (1.f + expf(-v)); }

// ---------------- kernel 1: per-node weight pools: W[n,j] = sum_e emb[n,e]*pool[e,j] --
__global__ void k_genw(const float* __restrict__ emb, const float* __restrict__ pool,
                       float* __restrict__ outw, int J) {
    int n = blockIdx.y;
    int j = blockIdx.x * blockDim.x + threadIdx.x;
    if (j >= J) return;
    float acc = 0.f;
#pragma unroll
    for (int e = 0; e < EE; e++) acc += emb[n * EE + e] * pool[e * J + j];
    outw[n * J + j] = acc;
}

// ---------------- kernel 2: build xs, hyper-net filter, nodevec ----------------
__global__ void k_prep(const float* __restrict__ x, const float* __restrict__ state,
                       const float* __restrict__ emb, const float* __restrict__ tim,
                       const float* __restrict__ day, const float* __restrict__ spd,
                       const float* __restrict__ occ,
                       const float* __restrict__ w1, const float* __restrict__ b1,
                       const float* __restrict__ w2, const float* __restrict__ b2,
                       const float* __restrict__ w3, const float* __restrict__ b3,
                       int is_update) {
    int idx = blockIdx.x * blockDim.x + threadIdx.x;
    if (idx >= BB * NN) return;
    int n = idx % NN;

    float c[CINx];
    c[0] = x[idx * 2 + 0];
    c[1] = x[idx * 2 + 1];
    const float* st = state + idx * DO;
    if (is_update) {
        const float* z = g_zr + idx * OG;   // z = zr[..., :64]
#pragma unroll
        for (int j = 0; j < DO; j++) c[2 + j] = z[j] * st[j];
    } else {
#pragma unroll
        for (int j = 0; j < DO; j++) c[2 + j] = st[j];
    }
    float* xo = g_xs + idx * CINx;
#pragma unroll
    for (int i = 0; i < CINx; i++) xo[i] = c[i];

    // fc1 (66->16) sigmoid
    float h1[16];
#pragma unroll
    for (int t = 0; t < 16; t++) h1[t] = b1[t];
    for (int i = 0; i < CINx; i++) {
        float ci = c[i];
#pragma unroll
        for (int t = 0; t < 16; t++) h1[t] += ci * w1[i * 16 + t];
    }
#pragma unroll
    for (int t = 0; t < 16; t++) h1[t] = sigm(h1[t]);

    // fc2 (16->2) sigmoid
    float h2[2];
#pragma unroll
    for (int u = 0; u < 2; u++) {
        float s = b2[u];
#pragma unroll
        for (int t = 0; t < 16; t++) s += h1[t] * w2[t * 2 + u];
        h2[u] = sigm(s);
    }

    // fc3 (2->10) no act; dyn modulated embedding; nodevec = tanh
    float* nvp = g_nv + idx * EE;
#pragma unroll
    for (int e = 0; e < EE; e++) {
        float f = b3[e] + h2[0] * w3[e] + h2[1] * w3[EE + e];
        float dyn = emb[n * EE + e] * tim[idx * EE + e] * day[idx * EE + e]
                  * spd[idx * EE + e] * occ[idx * EE + e];
        nvp[e] = tanhf(dyn * f);
    }
}

// ---------------- kernel 3: d[b,n] = rsqrt( sum_m relu(nv_n . nv_m) ) --------------
__global__ void k_degree() {
    __shared__ float s_nv[NN * EE];   // 35.3 KB: whole batch's nodevecs
    int b = blockIdx.y;
    const float* nvb = g_nv + b * NN * EE;
    for (int i = threadIdx.x; i < NN * EE; i += blockDim.x) s_nv[i] = nvb[i];
    __syncthreads();
    int n = blockIdx.x * blockDim.x + threadIdx.x;
    if (n >= NN) return;
    float my[EE];
#pragma unroll
    for (int e = 0; e < EE; e++) my[e] = s_nv[n * EE + e];
    float sum = 0.f;
    for (int m = 0; m < NN; m++) {
        float dot = 0.f;
#pragma unroll
        for (int e = 0; e < EE; e++) dot += my[e] * s_nv[m * EE + e];
        sum += fmaxf(dot, 0.f);
    }
    g_d[b * NN + n] = rsqrtf(sum);
}

// ---------------- kernel 4: dxs = d[m] * xs[m,c] ----------------
__global__ void k_scale() {
    int idx = blockIdx.x * blockDim.x + threadIdx.x;
    if (idx >= BB * NN * CINx) return;
    g_dxs[idx] = g_d[idx / CINx] * g_xs[idx];
}

// ---------------- kernel 5: y2 = xs - d_n * (relu(NV NV^T) @ dxs) ----------------
__global__ void k_lx() {
    __shared__ float s_nvr[TN * EE];
    __shared__ float s_nvm[TM * EE];
    __shared__ __align__(16) float s_dx[TM * CP];
    __shared__ float s_a[TN * TM];

    int b = blockIdx.y;
    int n0 = blockIdx.x * TN;
    int tid = threadIdx.x;
    const float* nvb = g_nv + b * NN * EE;

    for (int i = tid; i < TN * EE; i += blockDim.x) {
        int n = n0 + i / EE;
        s_nvr[i] = (n < NN) ? nvb[n * EE + i % EE] : 0.f;
    }

    int row = tid / CGc;
    int cg  = tid % CGc;
    float a0 = 0.f, a1 = 0.f, a2 = 0.f, a3 = 0.f;

    for (int mt = 0; mt < NN; mt += TM) {
        __syncthreads();   // protects s_nvr on iter 0, and prior-iter reads after
        for (int i = tid; i < TM * EE; i += blockDim.x) {
            int m = mt + i / EE;
            s_nvm[i] = (m < NN) ? nvb[m * EE + i % EE] : 0.f;
        }
        for (int i = tid; i < TM * CP; i += blockDim.x) {
            int m = mt + i / CP, c = i % CP;
            s_dx[i] = (m < NN && c < CINx) ? g_dxs[(b * NN + m) * CINx + c] : 0.f;
        }
        __syncthreads();
        // phase 1: adjacency tile, relu'd
        for (int idx = tid; idx < TN * TM; idx += blockDim.x) {
            int r = idx / TM, mm = idx % TM;
            float dot = 0.f;
#pragma unroll
            for (int e = 0; e < EE; e++) dot += s_nvr[r * EE + e] * s_nvm[mm * EE + e];
            s_a[idx] = fmaxf(dot, 0.f);
        }
        __syncthreads();
        // phase 2: acc += A_tile @ dxs_tile (4 channels per thread, float4)
#pragma unroll 4
        for (int mm = 0; mm < TM; mm++) {
            float a = s_a[row * TM + mm];
            const float4 v = *reinterpret_cast<const float4*>(&s_dx[mm * CP + cg * 4]);
            a0 += a * v.x; a1 += a * v.y; a2 += a * v.z; a3 += a * v.w;
        }
    }

    int n = n0 + row;
    if (n < NN) {
        float dn = g_d[b * NN + n];
        int base = (b * NN + n) * CINx;
        float vals[4] = {a0, a1, a2, a3};
        int c0 = cg * 4;
#pragma unroll
        for (int q = 0; q < 4; q++) {
            int c = c0 + q;
            if (c < CINx) g_y2[base + c] = g_xs[base + c] - dn * vals[q];
        }
    }
}

// ---------------- kernel 6: out[b,n,o] = sum_ki xg[b,n,k,i] W[n,k,i,o] + bias; epilogue --
// mode 0: zr = sigmoid(.)       mode 1: hc = tanh(.); out = r*state + (1-r)*hc
__global__ void k_out(const float* __restrict__ W, const float* __restrict__ bias,
                      const float* __restrict__ state, int Ot, int mode,
                      float* __restrict__ outp) {
    __shared__ __align__(16) float sW[2 * CINx * 64];   // W[n, :, :, og*64 .. og*64+63]
    __shared__ float sf[8][2 * CINx];                   // 8 batches x (xs | y2)

    int n  = blockIdx.y;
    int og = blockIdx.x;
    int tid = threadIdx.x;
    int ol  = tid & 63;     // local o
    int grp = tid >> 6;     // 0/1: which 4-batch slice

    for (int idx = tid; idx < 132 * 64; idx += 128) {
        int iki = idx >> 6, o = idx & 63;
        sW[idx] = W[(n * 132 + iki) * Ot + og * 64 + o];
    }
    float bval = bias[n * Ot + og * 64 + ol];

    for (int bt = 0; bt < 8; bt++) {
        __syncthreads();    // also fences sW load on first iteration
        for (int idx = tid; idx < 8 * 132; idx += 128) {
            int bb = idx / 132, ii = idx % 132;
            int base = ((bt * 8 + bb) * NN + n) * CINx;
            sf[bb][ii] = (ii < CINx) ? g_xs[base + ii] : g_y2[base + ii - CINx];
        }
        __syncthreads();
        float acc[4];
#pragma unroll
        for (int q = 0; q < 4; q++) acc[q] = bval;
        for (int ii = 0; ii < 132; ii++) {
            float w = sW[ii * 64 + ol];
#pragma unroll
            for (int q = 0; q < 4; q++) acc[q] += w * sf[grp * 4 + q][ii];
        }
#pragma unroll
        for (int q = 0; q < 4; q++) {
            int b = bt * 8 + grp * 4 + q;
            if (mode == 0) {
                g_zr[(b * NN + n) * OG + og * 64 + ol] = sigm(acc[q]);
            } else {
                float hc = tanhf(acc[q]);
                float r  = g_zr[(b * NN + n) * OG + 64 + ol];
                float st = state[(b * NN + n) * DO + ol];
                outp[(b * NN + n) * DO + ol] = r * st + (1.f - r) * hc;
            }
        }
    }
}

// ---------------- launch ----------------
extern "C" void kernel_launch(void* const* d_in, const int* in_sizes, int n_in,
                              void* d_out, int out_size) {
    const float* x     = (const float*)d_in[0];
    const float* state = (const float*)d_in[1];
    const float* emb   = (const float*)d_in[2];
    const float* tim   = (const float*)d_in[3];
    const float* day   = (const float*)d_in[4];
    const float* spd   = (const float*)d_in[5];
    const float* occ   = (const float*)d_in[6];
    const float* gwp   = (const float*)d_in[7];
    const float* gbp   = (const float*)d_in[8];
    const float* g1w = (const float*)d_in[9],  *g1b = (const float*)d_in[10];
    const float* g2w = (const float*)d_in[11], *g2b = (const float*)d_in[12];
    const float* g3w = (const float*)d_in[13], *g3b = (const float*)d_in[14];
    const float* uwp = (const float*)d_in[15], *ubp = (const float*)d_in[16];
    const float* u1w = (const float*)d_in[17], *u1b = (const float*)d_in[18];
    const float* u2w = (const float*)d_in[19], *u2b = (const float*)d_in[20];
    const float* u3w = (const float*)d_in[21], *u3b = (const float*)d_in[22];
    float* out = (float*)d_out;

    float *pWg, *pbg, *pWu, *pbu;
    cudaGetSymbolAddress((void**)&pWg, g_Wg);
    cudaGetSymbolAddress((void**)&pbg, g_bg);
    cudaGetSymbolAddress((void**)&pWu, g_Wu);
    cudaGetSymbolAddress((void**)&pbu, g_bu);

    // per-node weight pools (batch-independent, computed once per call)
    k_genw<<<dim3((2 * CINx * OG + 127) / 128, NN), 128>>>(emb, gwp, pWg, 2 * CINx * OG);
    k_genw<<<dim3(1, NN), 128>>>(emb, gbp, pbg, OG);
    k_genw<<<dim3((2 * CINx * OU + 127) / 128, NN), 128>>>(emb, uwp, pWu, 2 * CINx * OU);
    k_genw<<<dim3(1, NN), 128>>>(emb, ubp, pbu, OU);

    int nthreads = BB * NN;

    // --- gate DGCN ---
    k_prep<<<(nthreads + 127) / 128, 128>>>(x, state, emb, tim, day, spd, occ,
                                            g1w, g1b, g2w, g2b, g3w, g3b, 0);
    k_degree<<<dim3((NN + 255) / 256, BB), 256>>>();
    k_scale<<<(BB * NN * CINx + 255) / 256, 256>>>();
    k_lx<<<dim3((NN + TN - 1) / TN, BB), TN * CGc>>>();
    k_out<<<dim3(2, NN), 128>>>(pWg, pbg, state, OG, 0, nullptr);

    // --- update DGCN (cand input = [x, z*state]) + GRU epilogue ---
    k_prep<<<(nthreads + 127) / 128, 128>>>(x, state, emb, tim, day, spd, occ,
                                            u1w, u1b, u2w, u2b, u3w, u3b, 1);
    k_degree<<<dim3((NN + 255) / 256, BB), 256>>>();
    k_scale<<<(BB * NN * CINx + 255) / 256, 256>>>();
    k_lx<<<dim3((NN + TN - 1) / TN, BB), TN * CGc>>>();
    k_out<<<dim3(1, NN), 128>>>(pWu, pbu, state, OU, 1, out);
}

// round 2
// speedup vs baseline: 1.6492x; 1.6492x over previous
#include <cuda_runtime.h>

// Problem constants
#define BB   64
#define NN   883
#define EE   10
#define CINx 66     // DIN + DOUT
#define DO   64     // DOUT
#define OG   128    // gate output width (2*DOUT)
#define OU   64     // update output width

// L@x tiling
#define TN   64     // rows per block
#define TM   64     // m-tile
#define CP   72     // padded channel count (66 -> 72, /4 = 18 groups)
#define NCG  18     // channel groups of 4
#define NRG  16     // row groups of 4
#define LXT  (NCG * NRG)   // 288 threads

typedef unsigned long long ull;

// ---------------- scratch (device globals; no allocation allowed) ----------------
__device__ float g_Wg[NN * 2 * CINx * OG];   // per-node gate weights   (59.7 MB)
__device__ float g_bg[NN * OG];
__device__ float g_Wu[NN * 2 * CINx * OU];   // per-node update weights (29.8 MB)
__device__ float g_bu[NN * OU];
__device__ float g_xs[BB * NN * CINx];       // current DGCN input (concat)
__device__ float g_nv[BB * NN * EE];         // nodevec
__device__ float g_d[BB * NN];               // degree^-0.5
__device__ float g_y2[BB * NN * CINx];       // L @ xs
__device__ float g_zr[BB * NN * OG];         // sigmoid(gate out): z | r

__device__ __forceinline__ float sigm(float v) { return 1.f / (1.f + expf(-v)); }

__device__ __forceinline__ ull pk2(float a, float b) {
    ull r; asm("mov.b64 %0, {%1, %2};" : "=l"(r) : "f"(a), "f"(b)); return r;
}
__device__ __forceinline__ ull fma2(ull a, ull b, ull c) {
    ull d; asm("fma.rn.f32x2 %0, %1, %2, %3;" : "=l"(d) : "l"(a), "l"(b), "l"(c)); return d;
}
__device__ __forceinline__ float2 upk(ull v) {
    float2 f; asm("mov.b64 {%0, %1}, %2;" : "=f"(f.x), "=f"(f.y) : "l"(v)); return f;
}

// ---------------- kernel 1: per-node weight pools: W[n,j] = sum_e emb[n,e]*pool[e,j] --
__global__ void k_genw(const float* __restrict__ emb, const float* __restrict__ pool,
                       float* __restrict__ outw, int J) {
    int n = blockIdx.y;
    int j = blockIdx.x * blockDim.x + threadIdx.x;
    if (j >= J) return;
    float acc = 0.f;
#pragma unroll
    for (int e = 0; e < EE; e++) acc += emb[n * EE + e] * pool[e * J + j];
    outw[n * J + j] = acc;
}

// ---------------- kernel 2: build xs, hyper-net filter, nodevec ----------------
__global__ void k_prep(const float* __restrict__ x, const float* __restrict__ state,
                       const float* __restrict__ emb, const float* __restrict__ tim,
                       const float* __restrict__ day, const float* __restrict__ spd,
                       const float* __restrict__ occ,
                       const float* __restrict__ w1, const float* __restrict__ b1,
                       const float* __restrict__ w2, const float* __restrict__ b2,
                       const float* __restrict__ w3, const float* __restrict__ b3,
                       int is_update) {
    int idx = blockIdx.x * blockDim.x + threadIdx.x;
    if (idx >= BB * NN) return;
    int n = idx % NN;

    float c[CINx];
    c[0] = x[idx * 2 + 0];
    c[1] = x[idx * 2 + 1];
    const float* st = state + idx * DO;
    if (is_update) {
        const float* z = g_zr + idx * OG;   // z = zr[..., :64]
#pragma unroll
        for (int j = 0; j < DO; j++) c[2 + j] = z[j] * st[j];
    } else {
#pragma unroll
        for (int j = 0; j < DO; j++) c[2 + j] = st[j];
    }
    float* xo = g_xs + idx * CINx;
#pragma unroll
    for (int i = 0; i < CINx; i++) xo[i] = c[i];

    // fc1 (66->16) sigmoid
    float h1[16];
#pragma unroll
    for (int t = 0; t < 16; t++) h1[t] = b1[t];
    for (int i = 0; i < CINx; i++) {
        float ci = c[i];
#pragma unroll
        for (int t = 0; t < 16; t++) h1[t] += ci * w1[i * 16 + t];
    }
#pragma unroll
    for (int t = 0; t < 16; t++) h1[t] = sigm(h1[t]);

    // fc2 (16->2) sigmoid
    float h2[2];
#pragma unroll
    for (int u = 0; u < 2; u++) {
        float s = b2[u];
#pragma unroll
        for (int t = 0; t < 16; t++) s += h1[t] * w2[t * 2 + u];
        h2[u] = sigm(s);
    }

    // fc3 (2->10) no act; dyn modulated embedding; nodevec = tanh
    float* nvp = g_nv + idx * EE;
#pragma unroll
    for (int e = 0; e < EE; e++) {
        float f = b3[e] + h2[0] * w3[e] + h2[1] * w3[EE + e];
        float dyn = emb[n * EE + e] * tim[idx * EE + e] * day[idx * EE + e]
                  * spd[idx * EE + e] * occ[idx * EE + e];
        nvp[e] = tanhf(dyn * f);
    }
}

// ---------------- kernel 3: d[b,n] = rsqrt( sum_m relu(nv_n . nv_m) ) --------------
__global__ void k_degree() {
    __shared__ float s_nv[NN * EE];   // 35.3 KB: whole batch's nodevecs
    int b = blockIdx.y;
    const float* nvb = g_nv + b * NN * EE;
    for (int i = threadIdx.x; i < NN * EE; i += blockDim.x) s_nv[i] = nvb[i];
    __syncthreads();
    int n = blockIdx.x * blockDim.x + threadIdx.x;
    if (n >= NN) return;
    float2 my[5];
#pragma unroll
    for (int e = 0; e < 5; e++) my[e] = *(const float2*)(s_nv + n * EE + e * 2);
    float sum = 0.f;
#pragma unroll 2
    for (int m = 0; m < NN; m++) {
        const float2* row = (const float2*)(s_nv + m * EE);
        float dot = 0.f;
#pragma unroll
        for (int e = 0; e < 5; e++) {
            float2 p = row[e];
            dot += my[e].x * p.x + my[e].y * p.y;
        }
        sum += fmaxf(dot, 0.f);
    }
    g_d[b * NN + n] = rsqrtf(sum);
}

// ---------------- kernel 4: y2 = xs - d_n * (relu(NV NV^T) @ (d*xs)) ----------------
// Block: 64 rows (n) x all channels; thread: 4 rows x 4 channels, FFMA2 inner loop.
__global__ void __launch_bounds__(LXT, 2) k_lx() {
    __shared__ float s_nvr[TN * EE];                   // row nodevecs
    __shared__ float s_nvm[TM * EE];                   // m-tile nodevecs
    __shared__ __align__(16) float s_dx[TM * CP];      // d[m]*xs[m,c], padded
    __shared__ float s_a[TN * TM];                     // relu(A) tile

    int b = blockIdx.y;
    int n0 = blockIdx.x * TN;
    int tid = threadIdx.x;
    int rg = tid / NCG;       // 0..15
    int cg = tid % NCG;       // 0..17
    const float* nvb = g_nv + b * NN * EE;

    for (int i = tid; i < TN * EE; i += LXT) {
        int n = n0 + i / EE;
        s_nvr[i] = (n < NN) ? nvb[n * EE + i % EE] : 0.f;
    }
    __syncthreads();

    // this thread's 4 row nodevecs -> registers
    float nvr[4][EE];
#pragma unroll
    for (int q = 0; q < 4; q++)
#pragma unroll
        for (int e = 0; e < EE; e++) nvr[q][e] = s_nvr[(rg * 4 + q) * EE + e];

    ull acc[4][2];
#pragma unroll
    for (int q = 0; q < 4; q++) { acc[q][0] = 0ull; acc[q][1] = 0ull; }

    for (int mt = 0; mt < NN; mt += TM) {
        __syncthreads();   // protect s_nvm/s_dx/s_a reuse from prior iter
        for (int i = tid; i < TM * EE; i += LXT) {
            int m = mt + i / EE;
            s_nvm[i] = (m < NN) ? nvb[m * EE + i % EE] : 0.f;
        }
        for (int i = tid; i < TM * CP; i += LXT) {
            int m = mt + i / CP, c = i % CP;
            s_dx[i] = (m < NN && c < CINx)
                      ? g_d[b * NN + m] * g_xs[(b * NN + m) * CINx + c] : 0.f;
        }
        __syncthreads();

        // phase 1: adjacency tile rows rg*4..rg*4+3, mm = cg + 18k
#pragma unroll
        for (int k = 0; k < 4; k++) {
            int mm = cg + NCG * k;
            if (mm < TM) {
                float nm[EE];
#pragma unroll
                for (int e = 0; e < 5; e++) {
                    float2 p = *(const float2*)(s_nvm + mm * EE + e * 2);
                    nm[e * 2] = p.x; nm[e * 2 + 1] = p.y;
                }
#pragma unroll
                for (int q = 0; q < 4; q++) {
                    float dot = 0.f;
#pragma unroll
                    for (int e = 0; e < EE; e++) dot += nvr[q][e] * nm[e];
                    s_a[(rg * 4 + q) * TM + mm] = fmaxf(dot, 0.f);
                }
            }
        }
        __syncthreads();

        // phase 2: acc += A_tile @ dx_tile, FFMA2
#pragma unroll 4
        for (int mm = 0; mm < TM; mm++) {
            ulonglong2 v = *(const ulonglong2*)(s_dx + mm * CP + cg * 4);
#pragma unroll
            for (int q = 0; q < 4; q++) {
                float a = s_a[(rg * 4 + q) * TM + mm];
                ull pa = pk2(a, a);
                acc[q][0] = fma2(pa, v.x, acc[q][0]);
                acc[q][1] = fma2(pa, v.y, acc[q][1]);
            }
        }
    }

#pragma unroll
    for (int q = 0; q < 4; q++) {
        int n = n0 + rg * 4 + q;
        if (n >= NN) continue;
        float dn = g_d[b * NN + n];
        int base = (b * NN + n) * CINx;
        float2 f01 = upk(acc[q][0]);
        float2 f23 = upk(acc[q][1]);
        float vals[4] = {f01.x, f01.y, f23.x, f23.y};
        int c0 = cg * 4;
#pragma unroll
        for (int t = 0; t < 4; t++) {
            int c = c0 + t;
            if (c < CINx) g_y2[base + c] = g_xs[base + c] - dn * vals[t];
        }
    }
}

// ---------------- kernel 5: out[b,n,o] = sum_ki xg[b,n,k,i] W[n,k,i,o] + bias ------
// Block (og, n): 128 threads. Thread: one o, 8 batches; 16-batch chunks, xor-swizzled sf.
// mode 0: zr = sigmoid(.)       mode 1: hc = tanh(.); out = r*state + (1-r)*hc
__global__ void k_out(const float* __restrict__ W, const float* __restrict__ bias,
                      const float* __restrict__ state, int Ot, int mode,
                      float* __restrict__ outp) {
    __shared__ __align__(16) float sW[2 * CINx * 64];   // W[n,:,:, og*64..+63]
    __shared__ __align__(16) float sf[132 * 16];        // 16 batches, swizzled groups of 4

    int n  = blockIdx.y;
    int og = blockIdx.x;
    int tid = threadIdx.x;
    int ol  = tid & 63;     // local o
    int grp = tid >> 6;     // 0/1: batch half within chunk

    for (int idx = tid; idx < 132 * 64; idx += 128) {
        int iki = idx >> 6, o = idx & 63;
        sW[idx] = W[(n * 132 + iki) * Ot + og * 64 + o];
    }
    float bval = bias[n * Ot + og * 64 + ol];

    for (int bt = 0; bt < 4; bt++) {      // 4 chunks of 16 batches
        __syncthreads();    // fences sW load on first iter; sf reuse after
        for (int idx = tid; idx < 16 * 132; idx += 128) {
            int bb = idx / 132, ii = idx % 132;
            int base = ((bt * 16 + bb) * NN + n) * CINx;
            float v = (ii < CINx) ? g_xs[base + ii] : g_y2[base + ii - CINx];
            // group-of-4 xor swizzle: logical group L stored at physical L^(ii&3)
            int w = ii * 16 + ((((bb >> 2) ^ (ii & 3)) << 2) | (bb & 3));
            sf[w] = v;
        }
        __syncthreads();

        ull acc[4];
#pragma unroll
        for (int k = 0; k < 4; k++) acc[k] = pk2(bval, bval);

        for (int ii = 0; ii < 132; ii++) {
            float w = sW[ii * 64 + ol];
            ull wp = pk2(w, w);
            const ulonglong2* p = (const ulonglong2*)(sf + ii * 16);
            ulonglong2 v0 = p[(2 * grp) ^ (ii & 3)];       // logical batches 8grp..+3
            ulonglong2 v1 = p[(2 * grp + 1) ^ (ii & 3)];   // logical batches 8grp+4..+7
            acc[0] = fma2(wp, v0.x, acc[0]);
            acc[1] = fma2(wp, v0.y, acc[1]);
            acc[2] = fma2(wp, v1.x, acc[2]);
            acc[3] = fma2(wp, v1.y, acc[3]);
        }

#pragma unroll
        for (int k = 0; k < 4; k++) {
            float2 f = upk(acc[k]);
            float vv[2] = {f.x, f.y};
#pragma unroll
            for (int h = 0; h < 2; h++) {
                int b = bt * 16 + grp * 8 + k * 2 + h;
                if (mode == 0) {
                    g_zr[(b * NN + n) * OG + og * 64 + ol] = sigm(vv[h]);
                } else {
                    float hc = tanhf(vv[h]);
                    float r  = g_zr[(b * NN + n) * OG + 64 + ol];
                    float st = state[(b * NN + n) * DO + ol];
                    outp[(b * NN + n) * DO + ol] = r * st + (1.f - r) * hc;
                }
            }
        }
    }
}

// ---------------- launch ----------------
extern "C" void kernel_launch(void* const* d_in, const int* in_sizes, int n_in,
                              void* d_out, int out_size) {
    const float* x     = (const float*)d_in[0];
    const float* state = (const float*)d_in[1];
    const float* emb   = (const float*)d_in[2];
    const float* tim   = (const float*)d_in[3];
    const float* day   = (const float*)d_in[4];
    const float* spd   = (const float*)d_in[5];
    const float* occ   = (const float*)d_in[6];
    const float* gwp   = (const float*)d_in[7];
    const float* gbp   = (const float*)d_in[8];
    const float* g1w = (const float*)d_in[9],  *g1b = (const float*)d_in[10];
    const float* g2w = (const float*)d_in[11], *g2b = (const float*)d_in[12];
    const float* g3w = (const float*)d_in[13], *g3b = (const float*)d_in[14];
    const float* uwp = (const float*)d_in[15], *ubp = (const float*)d_in[16];
    const float* u1w = (const float*)d_in[17], *u1b = (const float*)d_in[18];
    const float* u2w = (const float*)d_in[19], *u2b = (const float*)d_in[20];
    const float* u3w = (const float*)d_in[21], *u3b = (const float*)d_in[22];
    float* out = (float*)d_out;

    float *pWg, *pbg, *pWu, *pbu;
    cudaGetSymbolAddress((void**)&pWg, g_Wg);
    cudaGetSymbolAddress((void**)&pbg, g_bg);
    cudaGetSymbolAddress((void**)&pWu, g_Wu);
    cudaGetSymbolAddress((void**)&pbu, g_bu);

    // per-node weight pools (batch-independent, computed once per call)
    k_genw<<<dim3((2 * CINx * OG + 127) / 128, NN), 128>>>(emb, gwp, pWg, 2 * CINx * OG);
    k_genw<<<dim3(1, NN), 128>>>(emb, gbp, pbg, OG);
    k_genw<<<dim3((2 * CINx * OU + 127) / 128, NN), 128>>>(emb, uwp, pWu, 2 * CINx * OU);
    k_genw<<<dim3(1, NN), 128>>>(emb, ubp, pbu, OU);

    int nthreads = BB * NN;

    // --- gate DGCN ---
    k_prep<<<(nthreads + 127) / 128, 128>>>(x, state, emb, tim, day, spd, occ,
                                            g1w, g1b, g2w, g2b, g3w, g3b, 0);
    k_degree<<<dim3((NN + 255) / 256, BB), 256>>>();
    k_lx<<<dim3((NN + TN - 1) / TN, BB), LXT>>>();
    k_out<<<dim3(2, NN), 128>>>(pWg, pbg, state, OG, 0, nullptr);

    // --- update DGCN (cand input = [x, z*state]) + GRU epilogue ---
    k_prep<<<(nthreads + 127) / 128, 128>>>(x, state, emb, tim, day, spd, occ,
                                            u1w, u1b, u2w, u2b, u3w, u3b, 1);
    k_degree<<<dim3((NN + 255) / 256, BB), 256>>>();
    k_lx<<<dim3((NN + TN - 1) / TN, BB), LXT>>>();
    k_out<<<dim3(1, NN), 128>>>(pWu, pbu, state, OU, 1, out);
}

// round 5
// speedup vs baseline: 1.7098x; 1.0367x over previous
#include <cuda_runtime.h>

// Problem constants
#define BB   64
#define NN   883
#define EE   10
#define CINx 66     // DIN + DOUT
#define DO   64     // DOUT
#define OG   128    // gate output width (2*DOUT)
#define OU   64     // update output width

// L@x tiling: block = 128 rows (n) x full channels; m-tiles of 48
#define TN   128
#define TM   48
#define CP   72     // padded channels (9 groups of 8)
#define LXT  160    // threads: phase1 uses 128, phase2 uses 144

typedef unsigned long long ull;

// ---------------- scratch (device globals; no allocation allowed) ----------------
__device__ float g_Wg[NN * 2 * CINx * OG];   // per-node gate weights   (59.7 MB)
__device__ float g_bg[NN * OG];
__device__ float g_Wu[NN * 2 * CINx * OU];   // per-node update weights (29.8 MB)
__device__ float g_bu[NN * OU];
__device__ float g_xs[BB * NN * CINx];       // current DGCN input (concat)
__device__ float g_nv[BB * NN * EE];         // nodevec
__device__ float g_d[BB * NN];               // degree^-0.5
__device__ float g_y2[BB * NN * CINx];       // L @ xs
__device__ float g_zr[BB * NN * OG];         // sigmoid(gate out): z | r

__device__ __forceinline__ float sigm(float v) { return 1.f / (1.f + expf(-v)); }

__device__ __forceinline__ ull pk2(float a, float b) {
    ull r; asm("mov.b64 %0, {%1, %2};" : "=l"(r) : "f"(a), "f"(b)); return r;
}
__device__ __forceinline__ ull fma2(ull a, ull b, ull c) {
    ull d; asm("fma.rn.f32x2 %0, %1, %2, %3;" : "=l"(d) : "l"(a), "l"(b), "l"(c)); return d;
}
__device__ __forceinline__ float2 upk(ull v) {
    float2 f; asm("mov.b64 {%0, %1}, %2;" : "=f"(f.x), "=f"(f.y) : "l"(v)); return f;
}

// ---------------- kernel 1: per-node weight pools ----------------
__global__ void k_genw(const float* __restrict__ emb, const float* __restrict__ pool,
                       float* __restrict__ outw, int J) {
    int n = blockIdx.y;
    int j = blockIdx.x * blockDim.x + threadIdx.x;
    if (j >= J) return;
    float acc = 0.f;
#pragma unroll
    for (int e = 0; e < EE; e++) acc += emb[n * EE + e] * pool[e * J + j];
    outw[n * J + j] = acc;
}

// ---------------- kernel 2: build xs, hyper-net filter, nodevec ----------------
__global__ void k_prep(const float* __restrict__ x, const float* __restrict__ state,
                       const float* __restrict__ emb, const float* __restrict__ tim,
                       const float* __restrict__ day, const float* __restrict__ spd,
                       const float* __restrict__ occ,
                       const float* __restrict__ w1, const float* __restrict__ b1,
                       const float* __restrict__ w2, const float* __restrict__ b2,
                       const float* __restrict__ w3, const float* __restrict__ b3,
                       int is_update) {
    int idx = blockIdx.x * blockDim.x + threadIdx.x;
    if (idx >= BB * NN) return;
    int n = idx % NN;

    float c[CINx];
    c[0] = x[idx * 2 + 0];
    c[1] = x[idx * 2 + 1];
    const float* st = state + idx * DO;
    if (is_update) {
        const float* z = g_zr + idx * OG;   // z = zr[..., :64]
#pragma unroll
        for (int j = 0; j < DO; j++) c[2 + j] = z[j] * st[j];
    } else {
#pragma unroll
        for (int j = 0; j < DO; j++) c[2 + j] = st[j];
    }
    float* xo = g_xs + idx * CINx;
#pragma unroll
    for (int i = 0; i < CINx; i++) xo[i] = c[i];

    // fc1 (66->16) sigmoid
    float h1[16];
#pragma unroll
    for (int t = 0; t < 16; t++) h1[t] = b1[t];
    for (int i = 0; i < CINx; i++) {
        float ci = c[i];
#pragma unroll
        for (int t = 0; t < 16; t++) h1[t] += ci * w1[i * 16 + t];
    }
#pragma unroll
    for (int t = 0; t < 16; t++) h1[t] = sigm(h1[t]);

    // fc2 (16->2) sigmoid
    float h2[2];
#pragma unroll
    for (int u = 0; u < 2; u++) {
        float s = b2[u];
#pragma unroll
        for (int t = 0; t < 16; t++) s += h1[t] * w2[t * 2 + u];
        h2[u] = sigm(s);
    }

    // fc3 (2->10); dyn modulated embedding; nodevec = tanh
    float* nvp = g_nv + idx * EE;
#pragma unroll
    for (int e = 0; e < EE; e++) {
        float f = b3[e] + h2[0] * w3[e] + h2[1] * w3[EE + e];
        float dyn = emb[n * EE + e] * tim[idx * EE + e] * day[idx * EE + e]
                  * spd[idx * EE + e] * occ[idx * EE + e];
        nvp[e] = tanhf(dyn * f);
    }
}

// ---------------- kernel 3: d[b,n] = rsqrt( sum_m relu(nv_n . nv_m) ) --------------
// 512 threads, 1 n/thread, 2 blocks per batch; row loads are warp-broadcast.
__global__ void k_degree() {
    __shared__ float s_nv[NN * EE];   // 35.3 KB
    int b = blockIdx.y;
    const float* nvb = g_nv + b * NN * EE;
    for (int i = threadIdx.x; i < NN * EE; i += blockDim.x) s_nv[i] = nvb[i];
    __syncthreads();
    int n = blockIdx.x * blockDim.x + threadIdx.x;
    if (n >= NN) return;
    ull my[5];
#pragma unroll
    for (int e = 0; e < 5; e++) {
        float2 p = *(const float2*)(s_nv + n * EE + e * 2);
        my[e] = pk2(p.x, p.y);
    }
    float sum = 0.f;
#pragma unroll 2
    for (int m = 0; m < NN; m++) {
        const float2* row = (const float2*)(s_nv + m * EE);
        ull d2 = 0ull;
#pragma unroll
        for (int e = 0; e < 5; e++) {
            float2 p = row[e];
            d2 = fma2(my[e], pk2(p.x, p.y), d2);
        }
        float2 f = upk(d2);
        sum += fmaxf(f.x + f.y, 0.f);
    }
    g_d[b * NN + n] = rsqrtf(sum);
}

// ---------------- kernel 4: y2 = xs - d_n * (relu(NV NV^T) @ (d*xs)) ----------------
// Phase 1: thread (tid<128) = one row n, nodevec in regs, s_nvm broadcast.
// Phase 2: thread (tid<144) = 8 rows x 8 channels; s_a transposed [mm][n].
__global__ void __launch_bounds__(LXT, 4) k_lx() {
    __shared__ float s_nvm[TM * EE];                   // m-tile nodevecs (1.9 KB)
    __shared__ __align__(16) float s_dx[TM * CP];      // d[m]*xs[m,c]  (13.5 KB)
    __shared__ __align__(16) float s_a[TM * TN];       // relu(A), [mm][n] (24 KB)

    int b = blockIdx.y;
    int n0 = blockIdx.x * TN;
    int tid = threadIdx.x;
    const float* nvb = g_nv + b * NN * EE;

    // phase-1 row nodevec in registers (packed)
    ull nvr[5];
    {
        int n = n0 + tid;
        if (tid < TN && n < NN) {
            const float2* p = (const float2*)(nvb + n * EE);
#pragma unroll
            for (int e = 0; e < 5; e++) { float2 f = p[e]; nvr[e] = pk2(f.x, f.y); }
        } else {
#pragma unroll
            for (int e = 0; e < 5; e++) nvr[e] = 0ull;
        }
    }

    int rg = tid / 9;     // 0..15  (8 rows each)
    int cg = tid % 9;     // 0..8   (8 channels each)
    bool p2 = tid < 144;

    ull acc[8][4];
#pragma unroll
    for (int q = 0; q < 8; q++)
#pragma unroll
        for (int t = 0; t < 4; t++) acc[q][t] = 0ull;

    for (int mt = 0; mt < NN; mt += TM) {
        __syncthreads();   // protect s_nvm/s_dx/s_a reuse
        for (int i = tid; i < TM * EE; i += LXT) {
            int m = mt + i / EE;
            s_nvm[i] = (m < NN) ? nvb[m * EE + i % EE] : 0.f;
        }
        for (int i = tid; i < TM * CP; i += LXT) {
            int m = mt + i / CP, c = i % CP;
            s_dx[i] = (m < NN && c < CINx)
                      ? g_d[b * NN + m] * g_xs[(b * NN + m) * CINx + c] : 0.f;
        }
        __syncthreads();

        // phase 1: A[mm][tid] for this tile
        if (tid < TN) {
#pragma unroll 2
            for (int mm = 0; mm < TM; mm++) {
                const float2* q = (const float2*)(s_nvm + mm * EE);
                ull d2 = 0ull;
#pragma unroll
                for (int e = 0; e < 5; e++) {
                    float2 p = q[e];          // warp-broadcast
                    d2 = fma2(nvr[e], pk2(p.x, p.y), d2);
                }
                float2 f = upk(d2);
                s_a[mm * TN + tid] = fmaxf(f.x + f.y, 0.f);
            }
        }
        __syncthreads();

        // phase 2: acc += A^T tile x dx tile (8 rows x 8 ch per thread)
        if (p2) {
#pragma unroll 1
            for (int mm = 0; mm < TM; mm++) {
                const float* dxp = s_dx + mm * CP + cg * 8;
                ulonglong2 v0 = *(const ulonglong2*)(dxp);
                ulonglong2 v1 = *(const ulonglong2*)(dxp + 4);
                const float* ap = s_a + mm * TN + rg * 8;
                float4 a0 = *(const float4*)(ap);
                float4 a1 = *(const float4*)(ap + 4);
                float ar[8] = {a0.x, a0.y, a0.z, a0.w, a1.x, a1.y, a1.z, a1.w};
#pragma unroll
                for (int q = 0; q < 8; q++) {
                    ull pa = pk2(ar[q], ar[q]);
                    acc[q][0] = fma2(pa, v0.x, acc[q][0]);
                    acc[q][1] = fma2(pa, v0.y, acc[q][1]);
                    acc[q][2] = fma2(pa, v1.x, acc[q][2]);
                    acc[q][3] = fma2(pa, v1.y, acc[q][3]);
                }
            }
        }
    }

    if (p2) {
#pragma unroll
        for (int q = 0; q < 8; q++) {
            int n = n0 + rg * 8 + q;
            if (n >= NN) continue;
            float dn = g_d[b * NN + n];
            int base = (b * NN + n) * CINx;
            float vals[8];
#pragma unroll
            for (int t = 0; t < 4; t++) {
                float2 f = upk(acc[q][t]);
                vals[t * 2] = f.x; vals[t * 2 + 1] = f.y;
            }
            int c0 = cg * 8;
#pragma unroll
            for (int t = 0; t < 8; t++) {
                int c = c0 + t;
                if (c < CINx) g_y2[base + c] = g_xs[base + c] - dn * vals[t];
            }
        }
    }
}

// ---------------- kernel 5: out[b,n,o] = sum_ki xg[b,n,k,i] W[n,k,i,o] + bias ------
__global__ void k_out(const float* __restrict__ W, const float* __restrict__ bias,
                      const float* __restrict__ state, int Ot, int mode,
                      float* __restrict__ outp) {
    __shared__ __align__(16) float sW[2 * CINx * 64];   // W[n,:,:, og*64..+63]
    __shared__ __align__(16) float sf[132 * 16];        // 16 batches, swizzled

    int n  = blockIdx.y;
    int og = blockIdx.x;
    int tid = threadIdx.x;
    int ol  = tid & 63;     // local o
    int grp = tid >> 6;     // 0/1

    for (int idx = tid; idx < 132 * 64; idx += 128) {
        int iki = idx >> 6, o = idx & 63;
        sW[idx] = W[(n * 132 + iki) * Ot + og * 64 + o];
    }
    float bval = bias[n * Ot + og * 64 + ol];

    for (int bt = 0; bt < 4; bt++) {      // 4 chunks of 16 batches
        __syncthreads();
        for (int idx = tid; idx < 16 * 132; idx += 128) {
            int bb = idx / 132, ii = idx % 132;
            int base = ((bt * 16 + bb) * NN + n) * CINx;
            float v = (ii < CINx) ? g_xs[base + ii] : g_y2[base + ii - CINx];
            int w = ii * 16 + ((((bb >> 2) ^ (ii & 3)) << 2) | (bb & 3));
            sf[w] = v;
        }
        __syncthreads();

        ull acc[4];
#pragma unroll
        for (int k = 0; k < 4; k++) acc[k] = pk2(bval, bval);

        for (int ii = 0; ii < 132; ii++) {
            float w = sW[ii * 64 + ol];
            ull wp = pk2(w, w);
            const ulonglong2* p = (const ulonglong2*)(sf + ii * 16);
            ulonglong2 v0 = p[(2 * grp) ^ (ii & 3)];
            ulonglong2 v1 = p[(2 * grp + 1) ^ (ii & 3)];
            acc[0] = fma2(wp, v0.x, acc[0]);
            acc[1] = fma2(wp, v0.y, acc[1]);
            acc[2] = fma2(wp, v1.x, acc[2]);
            acc[3] = fma2(wp, v1.y, acc[3]);
        }

#pragma unroll
        for (int k = 0; k < 4; k++) {
            float2 f = upk(acc[k]);
            float vv[2] = {f.x, f.y};
#pragma unroll
            for (int h = 0; h < 2; h++) {
                int b = bt * 16 + grp * 8 + k * 2 + h;
                if (mode == 0) {
                    g_zr[(b * NN + n) * OG + og * 64 + ol] = sigm(vv[h]);
                } else {
                    float hc = tanhf(vv[h]);
                    float r  = g_zr[(b * NN + n) * OG + 64 + ol];
                    float st = state[(b * NN + n) * DO + ol];
                    outp[(b * NN + n) * DO + ol] = r * st + (1.f - r) * hc;
                }
            }
        }
    }
}

// ---------------- launch ----------------
extern "C" void kernel_launch(void* const* d_in, const int* in_sizes, int n_in,
                              void* d_out, int out_size) {
    const float* x     = (const float*)d_in[0];
    const float* state = (const float*)d_in[1];
    const float* emb   = (const float*)d_in[2];
    const float* tim   = (const float*)d_in[3];
    const float* day   = (const float*)d_in[4];
    const float* spd   = (const float*)d_in[5];
    const float* occ   = (const float*)d_in[6];
    const float* gwp   = (const float*)d_in[7];
    const float* gbp   = (const float*)d_in[8];
    const float* g1w = (const float*)d_in[9],  *g1b = (const float*)d_in[10];
    const float* g2w = (const float*)d_in[11], *g2b = (const float*)d_in[12];
    const float* g3w = (const float*)d_in[13], *g3b = (const float*)d_in[14];
    const float* uwp = (const float*)d_in[15], *ubp = (const float*)d_in[16];
    const float* u1w = (const float*)d_in[17], *u1b = (const float*)d_in[18];
    const float* u2w = (const float*)d_in[19], *u2b = (const float*)d_in[20];
    const float* u3w = (const float*)d_in[21], *u3b = (const float*)d_in[22];
    float* out = (float*)d_out;

    float *pWg, *pbg, *pWu, *pbu;
    cudaGetSymbolAddress((void**)&pWg, g_Wg);
    cudaGetSymbolAddress((void**)&pbg, g_bg);
    cudaGetSymbolAddress((void**)&pWu, g_Wu);
    cudaGetSymbolAddress((void**)&pbu, g_bu);

    // per-node weight pools (batch-independent)
    k_genw<<<dim3((2 * CINx * OG + 127) / 128, NN), 128>>>(emb, gwp, pWg, 2 * CINx * OG);
    k_genw<<<dim3(1, NN), 128>>>(emb, gbp, pbg, OG);
    k_genw<<<dim3((2 * CINx * OU + 127) / 128, NN), 128>>>(emb, uwp, pWu, 2 * CINx * OU);
    k_genw<<<dim3(1, NN), 128>>>(emb, ubp, pbu, OU);

    int nthreads = BB * NN;

    // --- gate DGCN ---
    k_prep<<<(nthreads + 127) / 128, 128>>>(x, state, emb, tim, day, spd, occ,
                                            g1w, g1b, g2w, g2b, g3w, g3b, 0);
    k_degree<<<dim3(2, BB), 512>>>();
    k_lx<<<dim3((NN + TN - 1) / TN, BB), LXT>>>();
    k_out<<<dim3(2, NN), 128>>>(pWg, pbg, state, OG, 0, nullptr);

    // --- update DGCN (cand input = [x, z*state]) + GRU epilogue ---
    k_prep<<<(nthreads + 127) / 128, 128>>>(x, state, emb, tim, day, spd, occ,
                                            u1w, u1b, u2w, u2b, u3w, u3b, 1);
    k_degree<<<dim3(2, BB), 512>>>();
    k_lx<<<dim3((NN + TN - 1) / TN, BB), LXT>>>();
    k_out<<<dim3(1, NN), 128>>>(pWu, pbu, state, OU, 1, out);
}

// round 6
// speedup vs baseline: 1.8843x; 1.1020x over previous
#include <cuda_runtime.h>

// Problem constants
#define BB   64
#define NN   883
#define NPAD 912    // NN padded to multiple of TM (19*48)
#define EE   10
#define CINx 66     // DIN + DOUT
#define DO   64     // DOUT
#define OG   128    // gate output width (2*DOUT)
#define OU   64     // update output width

// L@x tiling: block = 128 rows (n) x full channels; m-tiles of 48
#define TN   128
#define TM   48
#define CP   72     // padded channels (9 groups of 8)
#define LXT  160    // threads: phase1 uses 128, phase2 uses 144

typedef unsigned long long ull;

// ---------------- scratch (device globals; no allocation allowed) ----------------
__device__ float g_Wg[NN * 2 * CINx * OG];   // per-node gate weights   (59.7 MB)
__device__ float g_bg[NN * OG];
__device__ float g_Wu[NN * 2 * CINx * OU];   // per-node update weights (29.8 MB)
__device__ float g_bu[NN * OU];
__device__ float g_xs[BB * NN * CINx];       // current DGCN input (concat)
__device__ __align__(16) float g_nv[BB * NPAD * EE];    // nodevec (padded, zero tail)
__device__ float g_d[BB * NN];               // degree^-0.5
__device__ __align__(16) float g_dxs[BB * NPAD * CP];   // d[m]*xs[m,c] (padded, zero tail)
__device__ float g_y2[BB * NN * CINx];       // L @ xs
__device__ float g_zr[BB * NN * OG];         // sigmoid(gate out): z | r

__device__ __forceinline__ float sigm(float v) { return 1.f / (1.f + expf(-v)); }

__device__ __forceinline__ ull pk2(float a, float b) {
    ull r; asm("mov.b64 %0, {%1, %2};" : "=l"(r) : "f"(a), "f"(b)); return r;
}
__device__ __forceinline__ ull fma2(ull a, ull b, ull c) {
    ull d; asm("fma.rn.f32x2 %0, %1, %2, %3;" : "=l"(d) : "l"(a), "l"(b), "l"(c)); return d;
}
__device__ __forceinline__ float2 upk(ull v) {
    float2 f; asm("mov.b64 {%0, %1}, %2;" : "=f"(f.x), "=f"(f.y) : "l"(v)); return f;
}

// ---------------- per-node weight pools ----------------
__global__ void k_genw(const float* __restrict__ emb, const float* __restrict__ pool,
                       float* __restrict__ outw, int J) {
    int n = blockIdx.y;
    int j = blockIdx.x * blockDim.x + threadIdx.x;
    if (j >= J) return;
    float acc = 0.f;
#pragma unroll
    for (int e = 0; e < EE; e++) acc += emb[n * EE + e] * pool[e * J + j];
    outw[n * J + j] = acc;
}

// ---------------- build xs, hyper-net filter, nodevec (padded rows zeroed) --------
__global__ void k_prep(const float* __restrict__ x, const float* __restrict__ state,
                       const float* __restrict__ emb, const float* __restrict__ tim,
                       const float* __restrict__ day, const float* __restrict__ spd,
                       const float* __restrict__ occ,
                       const float* __restrict__ w1, const float* __restrict__ b1,
                       const float* __restrict__ w2, const float* __restrict__ b2,
                       const float* __restrict__ w3, const float* __restrict__ b3,
                       int is_update) {
    int idx = blockIdx.x * blockDim.x + threadIdx.x;   // over BB*NPAD
    if (idx >= BB * NPAD) return;
    int n = idx % NPAD;
    int b = idx / NPAD;
    float* nvp = g_nv + idx * EE;
    if (n >= NN) {                    // zero padded tail rows
#pragma unroll
        for (int e = 0; e < EE; e++) nvp[e] = 0.f;
        return;
    }
    int bn = b * NN + n;

    float c[CINx];
    c[0] = x[bn * 2 + 0];
    c[1] = x[bn * 2 + 1];
    const float* st = state + bn * DO;
    if (is_update) {
        const float* z = g_zr + bn * OG;   // z = zr[..., :64]
#pragma unroll
        for (int j = 0; j < DO; j++) c[2 + j] = z[j] * st[j];
    } else {
#pragma unroll
        for (int j = 0; j < DO; j++) c[2 + j] = st[j];
    }
    float* xo = g_xs + bn * CINx;
#pragma unroll
    for (int i = 0; i < CINx; i++) xo[i] = c[i];

    // fc1 (66->16) sigmoid
    float h1[16];
#pragma unroll
    for (int t = 0; t < 16; t++) h1[t] = b1[t];
    for (int i = 0; i < CINx; i++) {
        float ci = c[i];
#pragma unroll
        for (int t = 0; t < 16; t++) h1[t] += ci * w1[i * 16 + t];
    }
#pragma unroll
    for (int t = 0; t < 16; t++) h1[t] = sigm(h1[t]);

    // fc2 (16->2) sigmoid
    float h2[2];
#pragma unroll
    for (int u = 0; u < 2; u++) {
        float s = b2[u];
#pragma unroll
        for (int t = 0; t < 16; t++) s += h1[t] * w2[t * 2 + u];
        h2[u] = sigm(s);
    }

    // fc3 (2->10); dyn modulated embedding; nodevec = tanh
#pragma unroll
    for (int e = 0; e < EE; e++) {
        float f = b3[e] + h2[0] * w3[e] + h2[1] * w3[EE + e];
        float dyn = emb[n * EE + e] * tim[bn * EE + e] * day[bn * EE + e]
                  * spd[bn * EE + e] * occ[bn * EE + e];
        nvp[e] = tanhf(dyn * f);
    }
}

// ---------------- d[b,n] = rsqrt( sum_m relu(nv_n . nv_m) ) ------------------------
__global__ void k_degree() {
    __shared__ __align__(16) float s_nv[NN * EE];   // 35.3 KB
    int b = blockIdx.y;
    const float* nvb = g_nv + b * NPAD * EE;
    for (int i = threadIdx.x; i < NN * EE; i += blockDim.x) s_nv[i] = nvb[i];
    __syncthreads();
    int n = blockIdx.x * blockDim.x + threadIdx.x;
    if (n >= NN) return;
    ull my[5];
    const ull* myp = (const ull*)(s_nv + n * EE);
#pragma unroll
    for (int e = 0; e < 5; e++) my[e] = myp[e];
    float sum = 0.f;
#pragma unroll 2
    for (int m = 0; m < NN; m++) {
        const ull* row = (const ull*)(s_nv + m * EE);
        ull d2 = 0ull;
#pragma unroll
        for (int e = 0; e < 5; e++) d2 = fma2(my[e], row[e], d2);
        float2 f = upk(d2);
        sum += fmaxf(f.x + f.y, 0.f);
    }
    g_d[b * NN + n] = rsqrtf(sum);
}

// ---------------- dxs = d[m]*xs[m,c] in padded layout (zero tails) -----------------
__global__ void k_scale() {
    int idx = blockIdx.x * blockDim.x + threadIdx.x;
    if (idx >= BB * NPAD * CP) return;
    int c = idx % CP;
    int r = idx / CP;
    int m = r % NPAD;
    int b = r / NPAD;
    float v = 0.f;
    if (m < NN && c < CINx)
        v = g_d[b * NN + m] * g_xs[(b * NN + m) * CINx + c];
    g_dxs[idx] = v;
}

// ---------------- y2 = xs - d_n * (relu(NV NV^T) @ (d*xs)) -------------------------
// Phase 1: thread (tid<128) = one row n, nodevec in regs, s_nvm broadcast.
// Phase 2: thread (tid<144) = 8 rows x 8 channels; s_a transposed [mm][n].
__global__ void __launch_bounds__(LXT, 3) k_lx() {
    __shared__ __align__(16) float s_nvm[TM * EE];     // 1.9 KB
    __shared__ __align__(16) float s_dx[TM * CP];      // 13.5 KB
    __shared__ __align__(16) float s_a[TM * TN];       // 24 KB

    int b = blockIdx.y;
    int n0 = blockIdx.x * TN;
    int tid = threadIdx.x;
    const float* nvb = g_nv + b * NPAD * EE;

    // phase-1 row nodevec in registers (packed); rows up to 895 < NPAD, zero-padded
    ull nvr[5];
    {
        int n = n0 + ((tid < TN) ? tid : 0);
        const ull* p = (const ull*)(nvb + n * EE);
#pragma unroll
        for (int e = 0; e < 5; e++) nvr[e] = p[e];
    }

    int rg = tid / 9;     // 0..15 for phase-2 threads (8 rows each)
    int cg = tid % 9;     // 0..8  (8 channels each)
    bool p2 = tid < 144;

    ull acc[8][4];
#pragma unroll
    for (int q = 0; q < 8; q++)
#pragma unroll
        for (int t = 0; t < 4; t++) acc[q][t] = 0ull;

    for (int mt = 0; mt < NPAD; mt += TM) {
        __syncthreads();   // protect s_nvm/s_dx/s_a reuse
        // branch-free float4 tile fills (padded global layout)
        {
            const float4* gn = (const float4*)(nvb + mt * EE);
            float4* sn = (float4*)s_nvm;
            for (int i = tid; i < TM * EE / 4; i += LXT) sn[i] = gn[i];
            const float4* gd = (const float4*)(g_dxs + (b * NPAD + mt) * CP);
            float4* sd = (float4*)s_dx;
#pragma unroll
            for (int i = tid; i < TM * CP / 4; i += LXT) sd[i] = gd[i];
        }
        __syncthreads();

        // phase 1: A[mm][tid] for this tile
        if (tid < TN) {
#pragma unroll 2
            for (int mm = 0; mm < TM; mm++) {
                const ull* q = (const ull*)(s_nvm + mm * EE);
                ull d2 = 0ull;
#pragma unroll
                for (int e = 0; e < 5; e++) d2 = fma2(nvr[e], q[e], d2);
                float2 f = upk(d2);
                s_a[mm * TN + tid] = fmaxf(f.x + f.y, 0.f);
            }
        }
        __syncthreads();

        // phase 2: acc += A^T tile x dx tile (8 rows x 8 ch per thread)
        if (p2) {
#pragma unroll 1
            for (int mm = 0; mm < TM; mm++) {
                const float* dxp = s_dx + mm * CP + cg * 8;
                ulonglong2 v0 = *(const ulonglong2*)(dxp);
                ulonglong2 v1 = *(const ulonglong2*)(dxp + 4);
                const float* ap = s_a + mm * TN + rg * 8;
                float4 a0 = *(const float4*)(ap);
                float4 a1 = *(const float4*)(ap + 4);
                float ar[8] = {a0.x, a0.y, a0.z, a0.w, a1.x, a1.y, a1.z, a1.w};
#pragma unroll
                for (int q = 0; q < 8; q++) {
                    ull pa = pk2(ar[q], ar[q]);
                    acc[q][0] = fma2(pa, v0.x, acc[q][0]);
                    acc[q][1] = fma2(pa, v0.y, acc[q][1]);
                    acc[q][2] = fma2(pa, v1.x, acc[q][2]);
                    acc[q][3] = fma2(pa, v1.y, acc[q][3]);
                }
            }
        }
    }

    if (p2) {
#pragma unroll
        for (int q = 0; q < 8; q++) {
            int n = n0 + rg * 8 + q;
            if (n >= NN) continue;
            float dn = g_d[b * NN + n];
            int base = (b * NN + n) * CINx;
            float vals[8];
#pragma unroll
            for (int t = 0; t < 4; t++) {
                float2 f = upk(acc[q][t]);
                vals[t * 2] = f.x; vals[t * 2 + 1] = f.y;
            }
            int c0 = cg * 8;
#pragma unroll
            for (int t = 0; t < 8; t++) {
                int c = c0 + t;
                if (c < CINx) g_y2[base + c] = g_xs[base + c] - dn * vals[t];
            }
        }
    }
}

// ---------------- out[b,n,o] = sum_ki xg[b,n,k,i] W[n,k,i,o] + bias ----------------
__global__ void k_out(const float* __restrict__ W, const float* __restrict__ bias,
                      const float* __restrict__ state, int Ot, int mode,
                      float* __restrict__ outp) {
    __shared__ __align__(16) float sW[2 * CINx * 64];   // W[n,:,:, og*64..+63]
    __shared__ __align__(16) float sf[132 * 16];        // 16 batches, swizzled

    int n  = blockIdx.y;
    int og = blockIdx.x;
    int tid = threadIdx.x;
    int ol  = tid & 63;     // local o
    int grp = tid >> 6;     // 0/1

    for (int idx = tid; idx < 132 * 64; idx += 128) {
        int iki = idx >> 6, o = idx & 63;
        sW[idx] = W[(n * 132 + iki) * Ot + og * 64 + o];
    }
    float bval = bias[n * Ot + og * 64 + ol];

    for (int bt = 0; bt < 4; bt++) {      // 4 chunks of 16 batches
        __syncthreads();
        for (int idx = tid; idx < 16 * 132; idx += 128) {
            int bb = idx / 132, ii = idx % 132;
            int base = ((bt * 16 + bb) * NN + n) * CINx;
            float v = (ii < CINx) ? g_xs[base + ii] : g_y2[base + ii - CINx];
            int w = ii * 16 + ((((bb >> 2) ^ (ii & 3)) << 2) | (bb & 3));
            sf[w] = v;
        }
        __syncthreads();

        ull acc[4];
#pragma unroll
        for (int k = 0; k < 4; k++) acc[k] = pk2(bval, bval);

        for (int ii = 0; ii < 132; ii++) {
            float w = sW[ii * 64 + ol];
            ull wp = pk2(w, w);
            const ulonglong2* p = (const ulonglong2*)(sf + ii * 16);
            ulonglong2 v0 = p[(2 * grp) ^ (ii & 3)];
            ulonglong2 v1 = p[(2 * grp + 1) ^ (ii & 3)];
            acc[0] = fma2(wp, v0.x, acc[0]);
            acc[1] = fma2(wp, v0.y, acc[1]);
            acc[2] = fma2(wp, v1.x, acc[2]);
            acc[3] = fma2(wp, v1.y, acc[3]);
        }

#pragma unroll
        for (int k = 0; k < 4; k++) {
            float2 f = upk(acc[k]);
            float vv[2] = {f.x, f.y};
#pragma unroll
            for (int h = 0; h < 2; h++) {
                int b = bt * 16 + grp * 8 + k * 2 + h;
                if (mode == 0) {
                    g_zr[(b * NN + n) * OG + og * 64 + ol] = sigm(vv[h]);
                } else {
                    float hc = tanhf(vv[h]);
                    float r  = g_zr[(b * NN + n) * OG + 64 + ol];
                    float st = state[(b * NN + n) * DO + ol];
                    outp[(b * NN + n) * DO + ol] = r * st + (1.f - r) * hc;
                }
            }
        }
    }
}

// ---------------- launch ----------------
// Order puts the gate k_lx at launch #6 so ncu's "-s 5 -c 1" window profiles it.
extern "C" void kernel_launch(void* const* d_in, const int* in_sizes, int n_in,
                              void* d_out, int out_size) {
    const float* x     = (const float*)d_in[0];
    const float* state = (const float*)d_in[1];
    const float* emb   = (const float*)d_in[2];
    const float* tim   = (const float*)d_in[3];
    const float* day   = (const float*)d_in[4];
    const float* spd   = (const float*)d_in[5];
    const float* occ   = (const float*)d_in[6];
    const float* gwp   = (const float*)d_in[7];
    const float* gbp   = (const float*)d_in[8];
    const float* g1w = (const float*)d_in[9],  *g1b = (const float*)d_in[10];
    const float* g2w = (const float*)d_in[11], *g2b = (const float*)d_in[12];
    const float* g3w = (const float*)d_in[13], *g3b = (const float*)d_in[14];
    const float* uwp = (const float*)d_in[15], *ubp = (const float*)d_in[16];
    const float* u1w = (const float*)d_in[17], *u1b = (const float*)d_in[18];
    const float* u2w = (const float*)d_in[19], *u2b = (const float*)d_in[20];
    const float* u3w = (const float*)d_in[21], *u3b = (const float*)d_in[22];
    float* out = (float*)d_out;

    float *pWg, *pbg, *pWu, *pbu;
    cudaGetSymbolAddress((void**)&pWg, g_Wg);
    cudaGetSymbolAddress((void**)&pbg, g_bg);
    cudaGetSymbolAddress((void**)&pWu, g_Wu);
    cudaGetSymbolAddress((void**)&pbu, g_bu);

    int npr = BB * NPAD;

    // --- gate DGCN ---
    k_prep<<<(npr + 127) / 128, 128>>>(x, state, emb, tim, day, spd, occ,          // 1
                                       g1w, g1b, g2w, g2b, g3w, g3b, 0);
    k_degree<<<dim3(2, BB), 512>>>();                                              // 2
    k_scale<<<(BB * NPAD * CP + 255) / 256, 256>>>();                              // 3
    k_genw<<<dim3((2 * CINx * OG + 127) / 128, NN), 128>>>(emb, gwp, pWg, 2 * CINx * OG); // 4
    k_genw<<<dim3(1, NN), 128>>>(emb, gbp, pbg, OG);                               // 5
    k_lx<<<dim3((NN + TN - 1) / TN, BB), LXT>>>();                                 // 6 <- ncu
    k_genw<<<dim3((2 * CINx * OU + 127) / 128, NN), 128>>>(emb, uwp, pWu, 2 * CINx * OU); // 7
    k_genw<<<dim3(1, NN), 128>>>(emb, ubp, pbu, OU);                               // 8
    k_out<<<dim3(2, NN), 128>>>(pWg, pbg, state, OG, 0, nullptr);                  // 9

    // --- update DGCN (cand input = [x, z*state]) + GRU epilogue ---
    k_prep<<<(npr + 127) / 128, 128>>>(x, state, emb, tim, day, spd, occ,          // 10
                                       u1w, u1b, u2w, u2b, u3w, u3b, 1);
    k_degree<<<dim3(2, BB), 512>>>();                                              // 11
    k_scale<<<(BB * NPAD * CP + 255) / 256, 256>>>();                              // 12
    k_lx<<<dim3((NN + TN - 1) / TN, BB), LXT>>>();                                 // 13
    k_out<<<dim3(1, NN), 128>>>(pWu, pbu, state, OU, 1, out);                      // 14
}

// round 7
// speedup vs baseline: 2.0466x; 1.0861x over previous
#include <cuda_runtime.h>

// Problem constants
#define BB   64
#define NN   883
#define NPAD 912    // NN padded to multiple of TM (19*48)
#define EE   10
#define CINx 66     // DIN + DOUT
#define DO   64     // DOUT
#define OG   128    // gate output width (2*DOUT)
#define OU   64     // update output width

// L@x tiling: block = 128 rows (n) x full channels; m-tiles of 48
#define TN   128
#define TM   48
#define CP   72     // padded channels (9 groups of 8)
#define LXT  160    // threads: phase1 uses 128, phase2 uses 144

typedef unsigned long long ull;

// ---------------- scratch (device globals; no allocation allowed) ----------------
__device__ __align__(16) float g_Wg[NN * 2 * CINx * OG];   // per-node gate weights
__device__ __align__(16) float g_bg[NN * OG];
__device__ __align__(16) float g_Wu[NN * 2 * CINx * OU];   // per-node update weights
__device__ __align__(16) float g_bu[NN * OU];
__device__ float g_xs[BB * NN * CINx];       // current DGCN input (concat)
__device__ __align__(16) float g_nv[BB * NPAD * EE];    // nodevec (padded, zero tail)
__device__ float g_d[BB * NN];               // degree^-0.5
__device__ __align__(16) float g_dxs[BB * NPAD * CP];   // d[m]*xs[m,c] (padded, zero tail)
__device__ float g_y2[BB * NN * CINx];       // L @ xs
__device__ float g_zr[BB * NN * OG];         // sigmoid(gate out): z | r

__device__ __forceinline__ float sigm(float v) { return 1.f / (1.f + expf(-v)); }

__device__ __forceinline__ ull pk2(float a, float b) {
    ull r; asm("mov.b64 %0, {%1, %2};" : "=l"(r) : "f"(a), "f"(b)); return r;
}
__device__ __forceinline__ ull fma2(ull a, ull b, ull c) {
    ull d; asm("fma.rn.f32x2 %0, %1, %2, %3;" : "=l"(d) : "l"(a), "l"(b), "l"(c)); return d;
}
__device__ __forceinline__ float2 upk(ull v) {
    float2 f; asm("mov.b64 {%0, %1}, %2;" : "=f"(f.x), "=f"(f.y) : "l"(v)); return f;
}

// ---------------- per-node weight pools (float4 vectorized) ----------------
// outw[n, j] = sum_e emb[n,e] * pool[e, j], processed 4 j's per thread.
__global__ void k_genw4(const float* __restrict__ emb, const float* __restrict__ pool,
                        float* __restrict__ outw, int J4) {
    int n = blockIdx.y;
    int j = blockIdx.x * blockDim.x + threadIdx.x;
    if (j >= J4) return;
    const float4* p4 = (const float4*)pool;
    float4 acc = make_float4(0.f, 0.f, 0.f, 0.f);
#pragma unroll
    for (int e = 0; e < EE; e++) {
        float w = emb[n * EE + e];
        float4 p = p4[e * J4 + j];
        acc.x += w * p.x; acc.y += w * p.y; acc.z += w * p.z; acc.w += w * p.w;
    }
    ((float4*)outw)[n * J4 + j] = acc;
}

// ---------------- build xs, hyper-net filter, nodevec (padded rows zeroed) --------
__global__ void k_prep(const float* __restrict__ x, const float* __restrict__ state,
                       const float* __restrict__ emb, const float* __restrict__ tim,
                       const float* __restrict__ day, const float* __restrict__ spd,
                       const float* __restrict__ occ,
                       const float* __restrict__ w1, const float* __restrict__ b1,
                       const float* __restrict__ w2, const float* __restrict__ b2,
                       const float* __restrict__ w3, const float* __restrict__ b3,
                       int is_update) {
    int idx = blockIdx.x * blockDim.x + threadIdx.x;   // over BB*NPAD
    if (idx >= BB * NPAD) return;
    int n = idx % NPAD;
    int b = idx / NPAD;
    float* nvp = g_nv + idx * EE;
    if (n >= NN) {                    // zero padded tail rows
#pragma unroll
        for (int e = 0; e < EE; e++) nvp[e] = 0.f;
        return;
    }
    int bn = b * NN + n;

    float c[CINx];
    c[0] = x[bn * 2 + 0];
    c[1] = x[bn * 2 + 1];
    const float* st = state + bn * DO;
    if (is_update) {
        const float* z = g_zr + bn * OG;   // z = zr[..., :64]
#pragma unroll
        for (int j = 0; j < DO; j++) c[2 + j] = z[j] * st[j];
    } else {
#pragma unroll
        for (int j = 0; j < DO; j++) c[2 + j] = st[j];
    }
    float* xo = g_xs + bn * CINx;
#pragma unroll
    for (int i = 0; i < CINx; i++) xo[i] = c[i];

    // fc1 (66->16) sigmoid
    float h1[16];
#pragma unroll
    for (int t = 0; t < 16; t++) h1[t] = b1[t];
    for (int i = 0; i < CINx; i++) {
        float ci = c[i];
#pragma unroll
        for (int t = 0; t < 16; t++) h1[t] += ci * w1[i * 16 + t];
    }
#pragma unroll
    for (int t = 0; t < 16; t++) h1[t] = sigm(h1[t]);

    // fc2 (16->2) sigmoid
    float h2[2];
#pragma unroll
    for (int u = 0; u < 2; u++) {
        float s = b2[u];
#pragma unroll
        for (int t = 0; t < 16; t++) s += h1[t] * w2[t * 2 + u];
        h2[u] = sigm(s);
    }

    // fc3 (2->10); dyn modulated embedding; nodevec = tanh
#pragma unroll
    for (int e = 0; e < EE; e++) {
        float f = b3[e] + h2[0] * w3[e] + h2[1] * w3[EE + e];
        float dyn = emb[n * EE + e] * tim[bn * EE + e] * day[bn * EE + e]
                  * spd[bn * EE + e] * occ[bn * EE + e];
        nvp[e] = tanhf(dyn * f);
    }
}

// ---------------- d[b,n] = rsqrt( sum_m relu(nv_n . nv_m) ) ------------------------
__global__ void k_degree() {
    __shared__ __align__(16) float s_nv[NN * EE];   // 35.3 KB
    int b = blockIdx.y;
    const float* nvb = g_nv + b * NPAD * EE;
    for (int i = threadIdx.x; i < NN * EE; i += blockDim.x) s_nv[i] = nvb[i];
    __syncthreads();
    int n = blockIdx.x * blockDim.x + threadIdx.x;
    if (n >= NN) return;
    ull my[5];
    const ull* myp = (const ull*)(s_nv + n * EE);
#pragma unroll
    for (int e = 0; e < 5; e++) my[e] = myp[e];
    float sum = 0.f;
#pragma unroll 2
    for (int m = 0; m < NN; m++) {
        const ull* row = (const ull*)(s_nv + m * EE);
        ull d2 = 0ull;
#pragma unroll
        for (int e = 0; e < 5; e++) d2 = fma2(my[e], row[e], d2);
        float2 f = upk(d2);
        sum += fmaxf(f.x + f.y, 0.f);
    }
    g_d[b * NN + n] = rsqrtf(sum);
}

// ---------------- dxs = d[m]*xs[m,c] padded layout; no int division ----------------
// grid (NPAD/8, BB), block (18, 8): thread = (c4, row-in-group)
__global__ void k_scale() {
    int b = blockIdx.y;
    int m = blockIdx.x * 8 + threadIdx.y;
    int c4 = threadIdx.x;                 // 0..17
    float4 v = make_float4(0.f, 0.f, 0.f, 0.f);
    if (m < NN) {
        float dm = g_d[b * NN + m];
        const float* xr = g_xs + (b * NN + m) * CINx;
        int c = c4 * 4;
        if (c + 3 < CINx) {
            v.x = dm * xr[c]; v.y = dm * xr[c + 1];
            v.z = dm * xr[c + 2]; v.w = dm * xr[c + 3];
        } else {
            if (c + 0 < CINx) v.x = dm * xr[c + 0];
            if (c + 1 < CINx) v.y = dm * xr[c + 1];
        }
    }
    ((float4*)g_dxs)[(b * NPAD + m) * (CP / 4) + c4] = v;
}

// ---------------- y2 = xs - d_n * (relu(NV NV^T) @ (d*xs)) -------------------------
// Phase 1: thread (tid<128) = one row n, nodevec in regs, s_nvm broadcast.
// Phase 2: thread (tid<144) = 8 rows x 8 channels; s_a transposed [mm][n].
__global__ void __launch_bounds__(LXT, 3) k_lx() {
    __shared__ __align__(16) float s_nvm[TM * EE];     // 1.9 KB
    __shared__ __align__(16) float s_dx[TM * CP];      // 13.5 KB
    __shared__ __align__(16) float s_a[TM * TN];       // 24 KB

    int b = blockIdx.y;
    int n0 = blockIdx.x * TN;
    int tid = threadIdx.x;
    const float* nvb = g_nv + b * NPAD * EE;

    // phase-1 row nodevec in registers (packed); rows up to 895 < NPAD, zero-padded
    ull nvr[5];
    {
        int n = n0 + ((tid < TN) ? tid : 0);
        const ull* p = (const ull*)(nvb + n * EE);
#pragma unroll
        for (int e = 0; e < 5; e++) nvr[e] = p[e];
    }

    int rg = tid / 9;     // 0..15 for phase-2 threads (8 rows each)
    int cg = tid % 9;     // 0..8  (8 channels each)
    bool p2 = tid < 144;

    ull acc[8][4];
#pragma unroll
    for (int q = 0; q < 8; q++)
#pragma unroll
        for (int t = 0; t < 4; t++) acc[q][t] = 0ull;

    for (int mt = 0; mt < NPAD; mt += TM) {
        __syncthreads();   // protect s_nvm/s_dx/s_a reuse
        // branch-free float4 tile fills (padded global layout)
        {
            const float4* gn = (const float4*)(nvb + mt * EE);
            float4* sn = (float4*)s_nvm;
            for (int i = tid; i < TM * EE / 4; i += LXT) sn[i] = gn[i];
            const float4* gd = (const float4*)(g_dxs + (b * NPAD + mt) * CP);
            float4* sd = (float4*)s_dx;
#pragma unroll
            for (int i = tid; i < TM * CP / 4; i += LXT) sd[i] = gd[i];
        }
        __syncthreads();

        // phase 1: A[mm][tid] for this tile
        if (tid < TN) {
#pragma unroll 2
            for (int mm = 0; mm < TM; mm++) {
                const ull* q = (const ull*)(s_nvm + mm * EE);
                ull d2 = 0ull;
#pragma unroll
                for (int e = 0; e < 5; e++) d2 = fma2(nvr[e], q[e], d2);
                float2 f = upk(d2);
                s_a[mm * TN + tid] = fmaxf(f.x + f.y, 0.f);
            }
        }
        __syncthreads();

        // phase 2: acc += A^T tile x dx tile (8 rows x 8 ch per thread)
        if (p2) {
#pragma unroll 1
            for (int mm = 0; mm < TM; mm++) {
                const float* dxp = s_dx + mm * CP + cg * 8;
                ulonglong2 v0 = *(const ulonglong2*)(dxp);
                ulonglong2 v1 = *(const ulonglong2*)(dxp + 4);
                const float* ap = s_a + mm * TN + rg * 8;
                float4 a0 = *(const float4*)(ap);
                float4 a1 = *(const float4*)(ap + 4);
                float ar[8] = {a0.x, a0.y, a0.z, a0.w, a1.x, a1.y, a1.z, a1.w};
#pragma unroll
                for (int q = 0; q < 8; q++) {
                    ull pa = pk2(ar[q], ar[q]);
                    acc[q][0] = fma2(pa, v0.x, acc[q][0]);
                    acc[q][1] = fma2(pa, v0.y, acc[q][1]);
                    acc[q][2] = fma2(pa, v1.x, acc[q][2]);
                    acc[q][3] = fma2(pa, v1.y, acc[q][3]);
                }
            }
        }
    }

    if (p2) {
#pragma unroll
        for (int q = 0; q < 8; q++) {
            int n = n0 + rg * 8 + q;
            if (n >= NN) continue;
            float dn = g_d[b * NN + n];
            int base = (b * NN + n) * CINx;
            float vals[8];
#pragma unroll
            for (int t = 0; t < 4; t++) {
                float2 f = upk(acc[q][t]);
                vals[t * 2] = f.x; vals[t * 2 + 1] = f.y;
            }
            int c0 = cg * 8;
#pragma unroll
            for (int t = 0; t < 8; t++) {
                int c = c0 + t;
                if (c < CINx) g_y2[base + c] = g_xs[base + c] - dn * vals[t];
            }
        }
    }
}

// ---------------- out[b,n,o] = sum_ki xg[b,n,k,i] W[n,k,i,o] + bias ----------------
__global__ void k_out(const float* __restrict__ W, const float* __restrict__ bias,
                      const float* __restrict__ state, int Ot, int mode,
                      float* __restrict__ outp) {
    __shared__ __align__(16) float sW[2 * CINx * 64];   // W[n,:,:, og*64..+63]
    __shared__ __align__(16) float sf[132 * 16];        // 16 batches, swizzled

    int n  = blockIdx.y;
    int og = blockIdx.x;
    int tid = threadIdx.x;
    int ol  = tid & 63;     // local o
    int grp = tid >> 6;     // 0/1

    // float4 weight tile load
    {
        const float4* W4 = (const float4*)(W + n * 132 * Ot + og * 64);
        int ot4 = Ot >> 2;
        float4* sW4 = (float4*)sW;
        for (int idx = tid; idx < 132 * 16; idx += 128) {
            int iki = idx >> 4, o4 = idx & 15;
            sW4[iki * 16 + o4] = W4[iki * ot4 + o4];
        }
    }
    float bval = bias[n * Ot + og * 64 + ol];

    for (int bt = 0; bt < 4; bt++) {      // 4 chunks of 16 batches
        __syncthreads();
        for (int idx = tid; idx < 16 * 132; idx += 128) {
            int bb = idx / 132, ii = idx % 132;
            int base = ((bt * 16 + bb) * NN + n) * CINx;
            float v = (ii < CINx) ? g_xs[base + ii] : g_y2[base + ii - CINx];
            int w = ii * 16 + ((((bb >> 2) ^ (ii & 3)) << 2) | (bb & 3));
            sf[w] = v;
        }
        __syncthreads();

        ull acc[4];
#pragma unroll
        for (int k = 0; k < 4; k++) acc[k] = pk2(bval, bval);

        for (int ii = 0; ii < 132; ii++) {
            float w = sW[ii * 64 + ol];
            ull wp = pk2(w, w);
            const ulonglong2* p = (const ulonglong2*)(sf + ii * 16);
            ulonglong2 v0 = p[(2 * grp) ^ (ii & 3)];
            ulonglong2 v1 = p[(2 * grp + 1) ^ (ii & 3)];
            acc[0] = fma2(wp, v0.x, acc[0]);
            acc[1] = fma2(wp, v0.y, acc[1]);
            acc[2] = fma2(wp, v1.x, acc[2]);
            acc[3] = fma2(wp, v1.y, acc[3]);
        }

#pragma unroll
        for (int k = 0; k < 4; k++) {
            float2 f = upk(acc[k]);
            float vv[2] = {f.x, f.y};
#pragma unroll
            for (int h = 0; h < 2; h++) {
                int b = bt * 16 + grp * 8 + k * 2 + h;
                if (mode == 0) {
                    g_zr[(b * NN + n) * OG + og * 64 + ol] = sigm(vv[h]);
                } else {
                    float hc = tanhf(vv[h]);
                    float r  = g_zr[(b * NN + n) * OG + 64 + ol];
                    float st = state[(b * NN + n) * DO + ol];
                    outp[(b * NN + n) * DO + ol] = r * st + (1.f - r) * hc;
                }
            }
        }
    }
}

// ---------------- launch ----------------
// Stream order places the gate k_lx at position 4: the ncu window captured
// position 4 last round, so this round it profiles the hot kernel.
extern "C" void kernel_launch(void* const* d_in, const int* in_sizes, int n_in,
                              void* d_out, int out_size) {
    const float* x     = (const float*)d_in[0];
    const float* state = (const float*)d_in[1];
    const float* emb   = (const float*)d_in[2];
    const float* tim   = (const float*)d_in[3];
    const float* day   = (const float*)d_in[4];
    const float* spd   = (const float*)d_in[5];
    const float* occ   = (const float*)d_in[6];
    const float* gwp   = (const float*)d_in[7];
    const float* gbp   = (const float*)d_in[8];
    const float* g1w = (const float*)d_in[9],  *g1b = (const float*)d_in[10];
    const float* g2w = (const float*)d_in[11], *g2b = (const float*)d_in[12];
    const float* g3w = (const float*)d_in[13], *g3b = (const float*)d_in[14];
    const float* uwp = (const float*)d_in[15], *ubp = (const float*)d_in[16];
    const float* u1w = (const float*)d_in[17], *u1b = (const float*)d_in[18];
    const float* u2w = (const float*)d_in[19], *u2b = (const float*)d_in[20];
    const float* u3w = (const float*)d_in[21], *u3b = (const float*)d_in[22];
    float* out = (float*)d_out;

    float *pWg, *pbg, *pWu, *pbu;
    cudaGetSymbolAddress((void**)&pWg, g_Wg);
    cudaGetSymbolAddress((void**)&pbg, g_bg);
    cudaGetSymbolAddress((void**)&pWu, g_Wu);
    cudaGetSymbolAddress((void**)&pbu, g_bu);

    int npr = BB * NPAD;

    // --- gate DGCN ---
    k_prep<<<(npr + 127) / 128, 128>>>(x, state, emb, tim, day, spd, occ,          // 1
                                       g1w, g1b, g2w, g2b, g3w, g3b, 0);
    k_degree<<<dim3(2, BB), 512>>>();                                              // 2
    k_scale<<<dim3(NPAD / 8, BB), dim3(18, 8)>>>();                                // 3
    k_lx<<<dim3((NN + TN - 1) / TN, BB), LXT>>>();                                 // 4 <- ncu
    k_genw4<<<dim3((2 * CINx * OG / 4 + 127) / 128, NN), 128>>>(emb, gwp, pWg,     // 5
                                                                2 * CINx * OG / 4);
    k_genw4<<<dim3(1, NN), 128>>>(emb, gbp, pbg, OG / 4);                          // 6
    k_out<<<dim3(2, NN), 128>>>(pWg, pbg, state, OG, 0, nullptr);                  // 7

    // --- update DGCN (cand input = [x, z*state]) + GRU epilogue ---
    k_prep<<<(npr + 127) / 128, 128>>>(x, state, emb, tim, day, spd, occ,          // 8
                                       u1w, u1b, u2w, u2b, u3w, u3b, 1);
    k_degree<<<dim3(2, BB), 512>>>();                                              // 9
    k_scale<<<dim3(NPAD / 8, BB), dim3(18, 8)>>>();                                // 10
    k_lx<<<dim3((NN + TN - 1) / TN, BB), LXT>>>();                                 // 11
    k_genw4<<<dim3((2 * CINx * OU / 4 + 127) / 128, NN), 128>>>(emb, uwp, pWu,     // 12
                                                                2 * CINx * OU / 4);
    k_genw4<<<dim3(1, NN), 128>>>(emb, ubp, pbu, OU / 4);                          // 13
    k_out<<<dim3(1, NN), 128>>>(pWu, pbu, state, OU, 1, out);                      // 14
}